// round 16
// baseline (speedup 1.0000x reference)
#include <cuda_runtime.h>
#include <cstdint>

// Problem constants
#define B_ 4
#define S_ 256
#define H_ 8
#define D_ 64
#define HID_ 512
#define M_ (B_ * S_)   // 1024 rows for all projections
#define SCALE_ 0.125f
#define TT_ 32         // t-tile per pipeline stage

// Scratch (allocation-free rule: __device__ globals)
__device__ float g_q[M_ * HID_];
__device__ float g_k[M_ * HID_];
__device__ float g_v[M_ * HID_];
__device__ float g_x[M_ * HID_];
__device__ float g_part[4 * M_ * HID_];   // split-K partials (O projection)

// ---------------------------------------------------------------------------
// Packed f32x2 helpers (sm_103a)
// ---------------------------------------------------------------------------
__device__ __forceinline__ unsigned long long pack2(float lo, float hi) {
    unsigned long long r;
    asm("mov.b64 %0, {%1, %2};" : "=l"(r) : "f"(lo), "f"(hi));
    return r;
}
__device__ __forceinline__ float2 unpack2(unsigned long long v) {
    float2 r;
    asm("mov.b64 {%0, %1}, %2;" : "=f"(r.x), "=f"(r.y) : "l"(v));
    return r;
}
__device__ __forceinline__ void ffma2(unsigned long long& d,
                                      unsigned long long a, unsigned long long b) {
    asm("fma.rn.f32x2 %0, %1, %2, %0;" : "+l"(d) : "l"(a), "l"(b));
}
__device__ __forceinline__ unsigned long long add2(unsigned long long a,
                                                   unsigned long long b) {
    unsigned long long r;
    asm("add.rn.f32x2 %0, %1, %2;" : "=l"(r) : "l"(a), "l"(b));
    return r;
}
__device__ __forceinline__ unsigned long long mul2(unsigned long long a,
                                                   unsigned long long b) {
    unsigned long long r;
    asm("mul.rn.f32x2 %0, %1, %2;" : "=l"(r) : "l"(a), "l"(b));
    return r;
}
__device__ __forceinline__ void cpasync16(unsigned int saddr, const void* g) {
    asm volatile("cp.async.cg.shared.global [%0], [%1], 16;" :: "r"(saddr), "l"(g));
}
__device__ __forceinline__ unsigned int smem_u32(const void* p) {
    return (unsigned int)__cvta_generic_to_shared(p);
}

struct G3 {
    const float* A[3];
    const float* W[3];
    const float* bias[3];
    float* C[3];
};
struct RedPtrs {
    const float* bias[3];
    float* out[3];
};

// ---------------------------------------------------------------------------
// GEMM 64x64 tile, BK=16, 4x4/thread, f32x2, double-buffered.
// A staged m-contiguous (LDS.128 -> 2 m-pair f32x2, no packing).
// B staged DUPLICATED (Bsd[kk][2j]=Bsd[kk][2j+1]=W) (LDS.128 -> 2 bcast
// f32x2, no packing). Inner loop: 3 LDS.128 + 8 FFMA2 per kk.
// blockIdx.z = gemm * nsl + slice.
//   nsl == 1 : full-K, writes C[gemm] with bias fused.
//   nsl  > 1 : split-K partial, writes part + z*(M_*HID_), no bias.
// ---------------------------------------------------------------------------
__global__ __launch_bounds__(256) void gemm64_db_kernel(
    G3 g, float* __restrict__ part, int nsl, int klen, int N, int K)
{
    const int z    = blockIdx.z;
    const int gemm = z / nsl;
    const int sl   = z - gemm * nsl;
    const float* __restrict__ A = g.A[gemm];
    const float* __restrict__ W = g.W[gemm];
    const int k0 = sl * klen;

    __shared__ __align__(16) float As[2][16][64];
    __shared__ __align__(16) float Bsd[2][16][128];   // duplicated columns

    const int bn = blockIdx.x * 64;
    const int bm = blockIdx.y * 64;
    const int tid = threadIdx.x;
    const int tx = tid & 15;
    const int ty = tid >> 4;

    const int aRow = tid >> 2;
    const int aCol = (tid & 3) * 4;
    const int bRow = tid >> 4;
    const int bCol = (tid & 15) * 4;

    unsigned long long acc[2][4] = {};   // [m-pair][j], each = (C[m][j], C[m+1][j])

    // prefetch k-block 0 into registers, stage into buffer 0
    float4 av = *reinterpret_cast<const float4*>(A + (size_t)(bm + aRow) * K + k0 + aCol);
    float4 bv = *reinterpret_cast<const float4*>(W + (size_t)(k0 + bRow) * N + bn + bCol);
    As[0][aCol + 0][aRow] = av.x;
    As[0][aCol + 1][aRow] = av.y;
    As[0][aCol + 2][aRow] = av.z;
    As[0][aCol + 3][aRow] = av.w;
    {
        float4 d0; d0.x = bv.x; d0.y = bv.x; d0.z = bv.y; d0.w = bv.y;
        float4 d1; d1.x = bv.z; d1.y = bv.z; d1.z = bv.w; d1.w = bv.w;
        *reinterpret_cast<float4*>(&Bsd[0][bRow][2 * bCol])     = d0;
        *reinterpret_cast<float4*>(&Bsd[0][bRow][2 * bCol + 4]) = d1;
    }
    __syncthreads();

    int buf = 0;
    for (int kb = k0; kb < k0 + klen; kb += 16) {
        const int kn = kb + 16;
        const bool more = (kn < k0 + klen);
        if (more) {
            av = *reinterpret_cast<const float4*>(A + (size_t)(bm + aRow) * K + kn + aCol);
            bv = *reinterpret_cast<const float4*>(W + (size_t)(kn + bRow) * N + bn + bCol);
        }

        #pragma unroll
        for (int kk = 0; kk < 16; kk++) {
            const ulonglong2 a2  = *reinterpret_cast<const ulonglong2*>(&As[buf][kk][ty * 4]);
            const ulonglong2 b01 = *reinterpret_cast<const ulonglong2*>(&Bsd[buf][kk][tx * 8]);
            const ulonglong2 b23 = *reinterpret_cast<const ulonglong2*>(&Bsd[buf][kk][tx * 8 + 4]);
            ffma2(acc[0][0], a2.x, b01.x);  ffma2(acc[0][1], a2.x, b01.y);
            ffma2(acc[0][2], a2.x, b23.x);  ffma2(acc[0][3], a2.x, b23.y);
            ffma2(acc[1][0], a2.y, b01.x);  ffma2(acc[1][1], a2.y, b01.y);
            ffma2(acc[1][2], a2.y, b23.x);  ffma2(acc[1][3], a2.y, b23.y);
        }

        if (more) {
            const int nb = buf ^ 1;
            As[nb][aCol + 0][aRow] = av.x;
            As[nb][aCol + 1][aRow] = av.y;
            As[nb][aCol + 2][aRow] = av.z;
            As[nb][aCol + 3][aRow] = av.w;
            float4 d0; d0.x = bv.x; d0.y = bv.x; d0.z = bv.y; d0.w = bv.y;
            float4 d1; d1.x = bv.z; d1.y = bv.z; d1.z = bv.w; d1.w = bv.w;
            *reinterpret_cast<float4*>(&Bsd[nb][bRow][2 * bCol])     = d0;
            *reinterpret_cast<float4*>(&Bsd[nb][bRow][2 * bCol + 4]) = d1;
        }
        __syncthreads();
        buf ^= 1;
    }

    // acc[p][j] = (C[ty*4+2p][j], C[ty*4+2p+1][j])
    const int col = bn + tx * 4;
    float4 orow[4];
    #pragma unroll
    for (int p = 0; p < 2; p++) {
        const float2 u0 = unpack2(acc[p][0]);
        const float2 u1 = unpack2(acc[p][1]);
        const float2 u2 = unpack2(acc[p][2]);
        const float2 u3 = unpack2(acc[p][3]);
        orow[2 * p].x     = u0.x; orow[2 * p].y     = u1.x;
        orow[2 * p].z     = u2.x; orow[2 * p].w     = u3.x;
        orow[2 * p + 1].x = u0.y; orow[2 * p + 1].y = u1.y;
        orow[2 * p + 1].z = u2.y; orow[2 * p + 1].w = u3.y;
    }

    if (nsl == 1) {
        float* __restrict__ C = g.C[gemm];
        const float4 bb = *reinterpret_cast<const float4*>(g.bias[gemm] + col);
        #pragma unroll
        for (int i = 0; i < 4; i++) {
            const int row = bm + ty * 4 + i;
            float4 o = orow[i];
            o.x += bb.x;  o.y += bb.y;  o.z += bb.z;  o.w += bb.w;
            *reinterpret_cast<float4*>(C + (size_t)row * N + col) = o;
        }
    } else {
        float* __restrict__ C = part + (size_t)z * (M_ * HID_);
        #pragma unroll
        for (int i = 0; i < 4; i++) {
            const int row = bm + ty * 4 + i;
            *reinterpret_cast<float4*>(C + (size_t)row * N + col) = orow[i];
        }
    }
}

// ---------------------------------------------------------------------------
// Split-K reduce + bias
// ---------------------------------------------------------------------------
__global__ __launch_bounds__(256) void reduce_bias_kernel(
    const float* __restrict__ part, RedPtrs rp, int nsl)
{
    const int g = blockIdx.y;
    const int i = blockIdx.x * 256 + threadIdx.x;        // float4 index
    const size_t stride4 = (size_t)(M_ * HID_) / 4;
    const float4* p = reinterpret_cast<const float4*>(part) + (size_t)g * nsl * stride4;

    float4 s = p[i];
    for (int j = 1; j < nsl; j++) {
        const float4 t = p[(size_t)j * stride4 + i];
        s.x += t.x;  s.y += t.y;  s.z += t.z;  s.w += t.w;
    }
    const float4 b4 = reinterpret_cast<const float4*>(rp.bias[g])[i & (HID_ / 4 - 1)];
    s.x += b4.x;  s.y += b4.y;  s.z += b4.z;  s.w += b4.w;
    reinterpret_cast<float4*>(rp.out[g])[i] = s;
}

// ---------------------------------------------------------------------------
// Fused GRPE attention, cp.async-pipelined streaming of spq/spk.
// (unchanged from R14/R15 — validated near HBM floor)
// ---------------------------------------------------------------------------
__global__ __launch_bounds__(256, 5) void attn_pipe_kernel(
    const float* __restrict__ qh, const float* __restrict__ kh,
    const float* __restrict__ vh, const float* __restrict__ abias,
    const float* __restrict__ spq, const float* __restrict__ spk,
    float* __restrict__ xo)
{
    const int s = blockIdx.x;
    const int h = blockIdx.y;
    const int b = blockIdx.z;
    const int tid = threadIdx.x;
    const int lane = tid & 31;
    const int w = tid >> 5;
    const int half = lane >> 4;
    const int l16 = lane & 15;

    __shared__ __align__(16) float4 stq[2][TT_ * 16];
    __shared__ __align__(16) float4 stk[2][TT_ * 16];
    __shared__ __align__(16) float sh_q[D_];
    __shared__ __align__(16) float sh_k[D_];
    __shared__ float sc[S_];
    __shared__ float sb[S_];
    __shared__ __align__(16) float pvp[16][D_];
    __shared__ float redm[8], reds[8];

    const int bh = b * H_ + h;
    const size_t rowbase = ((size_t)bh * S_ + s) * (size_t)(S_ * D_);
    const float* gq = spq + rowbase;
    const float* gk = spk + rowbase;

    {
        const unsigned int sq0 = smem_u32(&stq[0][0]);
        const unsigned int sk0 = smem_u32(&stk[0][0]);
        cpasync16(sq0 + tid * 16,           gq + tid * 4);
        cpasync16(sq0 + (tid + 256) * 16,   gq + (tid + 256) * 4);
        cpasync16(sk0 + tid * 16,           gk + tid * 4);
        cpasync16(sk0 + (tid + 256) * 16,   gk + (tid + 256) * 4);
    }
    asm volatile("cp.async.commit_group;" ::: "memory");

    {
        const float* qrow = qh + (size_t)(b * S_ + s) * HID_ + h * D_;
        const float* krow = kh + (size_t)(b * S_ + s) * HID_ + h * D_;
        if (tid < D_)            sh_q[tid]      = qrow[tid];
        else if (tid < 2 * D_)   sh_k[tid - D_] = krow[tid - D_];
        sb[tid] = abias[((size_t)bh * S_ + s) * S_ + tid];
    }
    __syncthreads();

    const float4 q4 = reinterpret_cast<const float4*>(sh_q)[l16];
    const float4 k4 = reinterpret_cast<const float4*>(sh_k)[l16];
    const unsigned long long q01 = pack2(q4.x, q4.y);
    const unsigned long long q23 = pack2(q4.z, q4.w);
    const unsigned long long k01 = pack2(k4.x, k4.y);
    const unsigned long long k23 = pack2(k4.z, k4.w);

    for (int j = 0; j < S_ / TT_; j++) {
        const int buf = j & 1;
        if (j + 1 < S_ / TT_) {
            const int nb = (j + 1) & 1;
            const float* gq1 = gq + (j + 1) * TT_ * D_;
            const float* gk1 = gk + (j + 1) * TT_ * D_;
            const unsigned int sq1 = smem_u32(&stq[nb][0]);
            const unsigned int sk1 = smem_u32(&stk[nb][0]);
            cpasync16(sq1 + tid * 16,         gq1 + tid * 4);
            cpasync16(sq1 + (tid + 256) * 16, gq1 + (tid + 256) * 4);
            cpasync16(sk1 + tid * 16,         gk1 + tid * 4);
            cpasync16(sk1 + (tid + 256) * 16, gk1 + (tid + 256) * 4);
        }
        asm volatile("cp.async.commit_group;" ::: "memory");
        asm volatile("cp.async.wait_group 1;" ::: "memory");
        __syncthreads();

        const ulonglong2* bq2 = reinterpret_cast<const ulonglong2*>(&stq[buf][0]);
        const ulonglong2* bk2 = reinterpret_cast<const ulonglong2*>(&stk[buf][0]);
        const int tlA = w * 4 + half;
        const int tlB = tlA + 2;
        const int tgA = j * TT_ + tlA;
        const int tgB = j * TT_ + tlB;

        const ulonglong2 kkA = reinterpret_cast<const ulonglong2*>(
            kh + (size_t)(b * S_ + tgA) * HID_ + h * D_)[l16];
        const ulonglong2 kkB = reinterpret_cast<const ulonglong2*>(
            kh + (size_t)(b * S_ + tgB) * HID_ + h * D_)[l16];
        const ulonglong2 aqA = bq2[tlA * 16 + l16];
        const ulonglong2 akA = bk2[tlA * 16 + l16];
        const ulonglong2 aqB = bq2[tlB * 16 + l16];
        const ulonglong2 akB = bk2[tlB * 16 + l16];

        unsigned long long pA = mul2(q01, add2(kkA.x, aqA.x));
        ffma2(pA, q23, add2(kkA.y, aqA.y));
        ffma2(pA, k01, akA.x);
        ffma2(pA, k23, akA.y);
        unsigned long long pB = mul2(q01, add2(kkB.x, aqB.x));
        ffma2(pB, q23, add2(kkB.y, aqB.y));
        ffma2(pB, k01, akB.x);
        ffma2(pB, k23, akB.y);

        const float2 fA = unpack2(pA);
        const float2 fB = unpack2(pB);
        float a = fA.x + fA.y;
        float c = fB.x + fB.y;
        #pragma unroll
        for (int o = 8; o > 0; o >>= 1) {
            a += __shfl_xor_sync(0xffffffffu, a, o);
            c += __shfl_xor_sync(0xffffffffu, c, o);
        }
        if (l16 == 0) {
            sc[tgA] = a * SCALE_ + sb[tgA];
            sc[tgB] = c * SCALE_ + sb[tgB];
        }
        __syncthreads();
    }

    const float v0 = sc[tid];
    float m = v0;
    #pragma unroll
    for (int o = 16; o > 0; o >>= 1) m = fmaxf(m, __shfl_xor_sync(0xffffffffu, m, o));
    if (lane == 0) redm[w] = m;
    __syncthreads();
    float gm = redm[0];
    #pragma unroll
    for (int j = 1; j < 8; j++) gm = fmaxf(gm, redm[j]);

    const float e = __expf(v0 - gm);
    sc[tid] = e;
    float sum = e;
    #pragma unroll
    for (int o = 16; o > 0; o >>= 1) sum += __shfl_xor_sync(0xffffffffu, sum, o);
    if (lane == 0) reds[w] = sum;
    __syncthreads();
    float tot = reds[0];
    #pragma unroll
    for (int j = 1; j < 8; j++) tot += reds[j];
    const float inv = 1.0f / tot;

    const int g  = tid >> 4;
    const int ld = tid & 15;
    const float* vbase = vh + (size_t)(b * S_) * HID_ + h * D_;
    unsigned long long acc01 = 0ull, acc23 = 0ull;
    #pragma unroll
    for (int i = 0; i < 16; i++) {
        const int t = g * 16 + i;
        const float wt = sc[t];
        const unsigned long long w2 = pack2(wt, wt);
        const ulonglong2 v2 = reinterpret_cast<const ulonglong2*>(
            vbase + (size_t)t * HID_)[ld];
        ffma2(acc01, w2, v2.x);
        ffma2(acc23, w2, v2.y);
    }
    {
        const float2 a01 = unpack2(acc01);
        const float2 a23 = unpack2(acc23);
        float4 o; o.x = a01.x; o.y = a01.y; o.z = a23.x; o.w = a23.y;
        *reinterpret_cast<float4*>(&pvp[g][ld * 4]) = o;
    }
    __syncthreads();

    const int d  = tid & 63;
    const int gq4 = tid >> 6;
    const float part = pvp[gq4 * 4 + 0][d] + pvp[gq4 * 4 + 1][d]
                     + pvp[gq4 * 4 + 2][d] + pvp[gq4 * 4 + 3][d];
    __syncthreads();
    pvp[gq4][d] = part;
    __syncthreads();

    if (tid < D_) {
        const float r = (pvp[0][tid] + pvp[1][tid] + pvp[2][tid] + pvp[3][tid]) * inv;
        xo[(size_t)(b * S_ + s) * HID_ + h * D_ + tid] = r;
    }
}

// ---------------------------------------------------------------------------
// Launch  (4 launches/call: qkv, attn, o-part, o-reduce)
// ---------------------------------------------------------------------------
extern "C" void kernel_launch(void* const* d_in, const int* in_sizes, int n_in,
                              void* d_out, int out_size)
{
    const float* q    = (const float*)d_in[0];
    const float* k    = (const float*)d_in[1];
    const float* v    = (const float*)d_in[2];
    const float* ab   = (const float*)d_in[3];
    const float* spq  = (const float*)d_in[4];
    const float* spk  = (const float*)d_in[5];
    const float* Wq   = (const float*)d_in[6];
    const float* bq   = (const float*)d_in[7];
    const float* Wk   = (const float*)d_in[8];
    const float* bk   = (const float*)d_in[9];
    const float* Wv   = (const float*)d_in[10];
    const float* bv   = (const float*)d_in[11];
    const float* Wo   = (const float*)d_in[12];
    const float* bo   = (const float*)d_in[13];
    float* out        = (float*)d_out;

    void *pq = nullptr, *pk = nullptr, *pv = nullptr, *px = nullptr, *pp = nullptr;
    cudaGetSymbolAddress(&pq, g_q);
    cudaGetSymbolAddress(&pk, g_k);
    cudaGetSymbolAddress(&pv, g_v);
    cudaGetSymbolAddress(&px, g_x);
    cudaGetSymbolAddress(&pp, g_part);

    // ---- QKV projections: full-K, bias fused, one launch (384 CTAs) ----
    G3 qkv;
    qkv.A[0] = q;  qkv.A[1] = k;  qkv.A[2] = v;
    qkv.W[0] = Wq; qkv.W[1] = Wk; qkv.W[2] = Wv;
    qkv.bias[0] = bq; qkv.bias[1] = bk; qkv.bias[2] = bv;
    qkv.C[0] = (float*)pq; qkv.C[1] = (float*)pk; qkv.C[2] = (float*)pv;
    gemm64_db_kernel<<<dim3(HID_ / 64, M_ / 64, 3), 256>>>(
        qkv, (float*)pp, 1, 512, HID_, HID_);

    // ---- attention: cp.async-pipelined, one CTA per (b,h,s) ----
    const dim3 ga(S_, H_, B_);    // 8192 CTAs
    attn_pipe_kernel<<<ga, 256>>>((const float*)pq, (const float*)pk, (const float*)pv,
                                  ab, spq, spk, (float*)px);

    // ---- O projection: split-K2 (256 CTAs) + reduce ----
    G3 og;
    og.A[0] = (const float*)px; og.A[1] = og.A[0]; og.A[2] = og.A[0];
    og.W[0] = Wo; og.W[1] = Wo; og.W[2] = Wo;
    og.bias[0] = bo; og.bias[1] = bo; og.bias[2] = bo;
    og.C[0] = out; og.C[1] = out; og.C[2] = out;
    gemm64_db_kernel<<<dim3(HID_ / 64, M_ / 64, 2), 256>>>(
        og, (float*)pp, 2, 256, HID_, HID_);

    RedPtrs r2;
    r2.bias[0] = bo; r2.bias[1] = bo; r2.bias[2] = bo;
    r2.out[0] = out; r2.out[1] = out; r2.out[2] = out;
    reduce_bias_kernel<<<dim3(M_ * HID_ / 4 / 256, 1), 256>>>((const float*)pp, r2, 2);
}

// round 17
// speedup vs baseline: 1.0388x; 1.0388x over previous
#include <cuda_runtime.h>
#include <cstdint>

// Problem constants
#define B_ 4
#define S_ 256
#define H_ 8
#define D_ 64
#define HID_ 512
#define M_ (B_ * S_)   // 1024 rows for all projections
#define SCALE_ 0.125f
#define TT_ 32         // t-tile per pipeline stage

// Scratch (allocation-free rule: __device__ globals)
__device__ float g_q[M_ * HID_];
__device__ float g_k[M_ * HID_];
__device__ float g_v[M_ * HID_];
__device__ float g_x[M_ * HID_];
__device__ float g_part[4 * M_ * HID_];   // split-K partials (O projection)

// ---------------------------------------------------------------------------
// Packed f32x2 helpers (sm_103a)
// ---------------------------------------------------------------------------
__device__ __forceinline__ unsigned long long pack2(float lo, float hi) {
    unsigned long long r;
    asm("mov.b64 %0, {%1, %2};" : "=l"(r) : "f"(lo), "f"(hi));
    return r;
}
__device__ __forceinline__ float2 unpack2(unsigned long long v) {
    float2 r;
    asm("mov.b64 {%0, %1}, %2;" : "=f"(r.x), "=f"(r.y) : "l"(v));
    return r;
}
__device__ __forceinline__ void ffma2(unsigned long long& d,
                                      unsigned long long a, unsigned long long b) {
    asm("fma.rn.f32x2 %0, %1, %2, %0;" : "+l"(d) : "l"(a), "l"(b));
}
__device__ __forceinline__ unsigned long long add2(unsigned long long a,
                                                   unsigned long long b) {
    unsigned long long r;
    asm("add.rn.f32x2 %0, %1, %2;" : "=l"(r) : "l"(a), "l"(b));
    return r;
}
__device__ __forceinline__ unsigned long long mul2(unsigned long long a,
                                                   unsigned long long b) {
    unsigned long long r;
    asm("mul.rn.f32x2 %0, %1, %2;" : "=l"(r) : "l"(a), "l"(b));
    return r;
}
__device__ __forceinline__ void cpasync16(unsigned int saddr, const void* g) {
    asm volatile("cp.async.cg.shared.global [%0], [%1], 16;" :: "r"(saddr), "l"(g));
}
__device__ __forceinline__ unsigned int smem_u32(const void* p) {
    return (unsigned int)__cvta_generic_to_shared(p);
}

struct G3 {
    const float* A[3];
    const float* W[3];
    const float* bias[3];
    float* C[3];
};
struct RedPtrs {
    const float* bias[3];
    float* out[3];
};

// ---------------------------------------------------------------------------
// GEMM 64x64 tile, BK=16, 2m x 8n/thread, f32x2, double-buffered.
// Same staging layout as the validated R15 kernel; only the microtile
// changed (halves the a-dup packing, same crossbar phases).
// Per kk: LDS.64(A bcast) + 2x LDS.128(B, 256B span) + 2 pack + 8 FFMA2.
// blockIdx.z = gemm * nsl + slice.
//   nsl == 1 : full-K, writes C[gemm] with bias fused.
//   nsl  > 1 : split-K partial, writes part + z*(M_*HID_), no bias.
// ---------------------------------------------------------------------------
__global__ __launch_bounds__(256) void gemm64_db_kernel(
    G3 g, float* __restrict__ part, int nsl, int klen, int N, int K)
{
    const int z    = blockIdx.z;
    const int gemm = z / nsl;
    const int sl   = z - gemm * nsl;
    const float* __restrict__ A = g.A[gemm];
    const float* __restrict__ W = g.W[gemm];
    const int k0 = sl * klen;

    __shared__ __align__(16) float As[2][16][64];   // As[kk][m] (m-contiguous)
    __shared__ __align__(16) float Bs[2][16][64];   // Bs[kk][n]

    const int bn = blockIdx.x * 64;
    const int bm = blockIdx.y * 64;
    const int tid = threadIdx.x;
    const int tx = tid & 7;       // n-group: 8 cols
    const int ty = tid >> 3;      // m-group: 2 rows (0..31)

    const int aRow = tid >> 2;
    const int aCol = (tid & 3) * 4;
    const int bRow = tid >> 4;
    const int bCol = (tid & 15) * 4;

    unsigned long long acc[2][4] = {};   // [mi][np]: (C[m][2np], C[m][2np+1])

    // prefetch k-block 0 into registers, stage into buffer 0
    float4 av = *reinterpret_cast<const float4*>(A + (size_t)(bm + aRow) * K + k0 + aCol);
    float4 bv = *reinterpret_cast<const float4*>(W + (size_t)(k0 + bRow) * N + bn + bCol);
    As[0][aCol + 0][aRow] = av.x;
    As[0][aCol + 1][aRow] = av.y;
    As[0][aCol + 2][aRow] = av.z;
    As[0][aCol + 3][aRow] = av.w;
    *reinterpret_cast<float4*>(&Bs[0][bRow][bCol]) = bv;
    __syncthreads();

    int buf = 0;
    for (int kb = k0; kb < k0 + klen; kb += 16) {
        const int kn = kb + 16;
        const bool more = (kn < k0 + klen);
        if (more) {
            av = *reinterpret_cast<const float4*>(A + (size_t)(bm + aRow) * K + kn + aCol);
            bv = *reinterpret_cast<const float4*>(W + (size_t)(kn + bRow) * N + bn + bCol);
        }

        #pragma unroll
        for (int kk = 0; kk < 16; kk++) {
            const float2 a2 = *reinterpret_cast<const float2*>(&As[buf][kk][ty * 2]);
            const ulonglong2 b01 = *reinterpret_cast<const ulonglong2*>(&Bs[buf][kk][tx * 8]);
            const ulonglong2 b23 = *reinterpret_cast<const ulonglong2*>(&Bs[buf][kk][tx * 8 + 4]);
            const unsigned long long a0 = pack2(a2.x, a2.x);
            const unsigned long long a1 = pack2(a2.y, a2.y);
            ffma2(acc[0][0], a0, b01.x);  ffma2(acc[0][1], a0, b01.y);
            ffma2(acc[0][2], a0, b23.x);  ffma2(acc[0][3], a0, b23.y);
            ffma2(acc[1][0], a1, b01.x);  ffma2(acc[1][1], a1, b01.y);
            ffma2(acc[1][2], a1, b23.x);  ffma2(acc[1][3], a1, b23.y);
        }

        if (more) {
            const int nb = buf ^ 1;
            As[nb][aCol + 0][aRow] = av.x;
            As[nb][aCol + 1][aRow] = av.y;
            As[nb][aCol + 2][aRow] = av.z;
            As[nb][aCol + 3][aRow] = av.w;
            *reinterpret_cast<float4*>(&Bs[nb][bRow][bCol]) = bv;
        }
        __syncthreads();
        buf ^= 1;
    }

    // Thread owns rows bm + ty*2 + {0,1}, cols bn + tx*8 + [0,8)
    const int col = bn + tx * 8;
    if (nsl == 1) {
        float* __restrict__ C = g.C[gemm];
        const float4 bb0 = *reinterpret_cast<const float4*>(g.bias[gemm] + col);
        const float4 bb1 = *reinterpret_cast<const float4*>(g.bias[gemm] + col + 4);
        #pragma unroll
        for (int mi = 0; mi < 2; mi++) {
            const int row = bm + ty * 2 + mi;
            const float2 u0 = unpack2(acc[mi][0]);
            const float2 u1 = unpack2(acc[mi][1]);
            const float2 u2 = unpack2(acc[mi][2]);
            const float2 u3 = unpack2(acc[mi][3]);
            float4 o0, o1;
            o0.x = u0.x + bb0.x;  o0.y = u0.y + bb0.y;
            o0.z = u1.x + bb0.z;  o0.w = u1.y + bb0.w;
            o1.x = u2.x + bb1.x;  o1.y = u2.y + bb1.y;
            o1.z = u3.x + bb1.z;  o1.w = u3.y + bb1.w;
            *reinterpret_cast<float4*>(C + (size_t)row * N + col)     = o0;
            *reinterpret_cast<float4*>(C + (size_t)row * N + col + 4) = o1;
        }
    } else {
        float* __restrict__ C = part + (size_t)z * (M_ * HID_);
        #pragma unroll
        for (int mi = 0; mi < 2; mi++) {
            const int row = bm + ty * 2 + mi;
            const float2 u0 = unpack2(acc[mi][0]);
            const float2 u1 = unpack2(acc[mi][1]);
            const float2 u2 = unpack2(acc[mi][2]);
            const float2 u3 = unpack2(acc[mi][3]);
            float4 o0, o1;
            o0.x = u0.x;  o0.y = u0.y;  o0.z = u1.x;  o0.w = u1.y;
            o1.x = u2.x;  o1.y = u2.y;  o1.z = u3.x;  o1.w = u3.y;
            *reinterpret_cast<float4*>(C + (size_t)row * N + col)     = o0;
            *reinterpret_cast<float4*>(C + (size_t)row * N + col + 4) = o1;
        }
    }
}

// ---------------------------------------------------------------------------
// Split-K reduce + bias
// ---------------------------------------------------------------------------
__global__ __launch_bounds__(256) void reduce_bias_kernel(
    const float* __restrict__ part, RedPtrs rp, int nsl)
{
    const int g = blockIdx.y;
    const int i = blockIdx.x * 256 + threadIdx.x;        // float4 index
    const size_t stride4 = (size_t)(M_ * HID_) / 4;
    const float4* p = reinterpret_cast<const float4*>(part) + (size_t)g * nsl * stride4;

    float4 s = p[i];
    for (int j = 1; j < nsl; j++) {
        const float4 t = p[(size_t)j * stride4 + i];
        s.x += t.x;  s.y += t.y;  s.z += t.z;  s.w += t.w;
    }
    const float4 b4 = reinterpret_cast<const float4*>(rp.bias[g])[i & (HID_ / 4 - 1)];
    s.x += b4.x;  s.y += b4.y;  s.z += b4.z;  s.w += b4.w;
    reinterpret_cast<float4*>(rp.out[g])[i] = s;
}

// ---------------------------------------------------------------------------
// Fused GRPE attention, cp.async-pipelined streaming of spq/spk.
// (byte-identical to R15 — validated near HBM floor)
// ---------------------------------------------------------------------------
__global__ __launch_bounds__(256, 5) void attn_pipe_kernel(
    const float* __restrict__ qh, const float* __restrict__ kh,
    const float* __restrict__ vh, const float* __restrict__ abias,
    const float* __restrict__ spq, const float* __restrict__ spk,
    float* __restrict__ xo)
{
    const int s = blockIdx.x;
    const int h = blockIdx.y;
    const int b = blockIdx.z;
    const int tid = threadIdx.x;
    const int lane = tid & 31;
    const int w = tid >> 5;
    const int half = lane >> 4;
    const int l16 = lane & 15;

    __shared__ __align__(16) float4 stq[2][TT_ * 16];
    __shared__ __align__(16) float4 stk[2][TT_ * 16];
    __shared__ __align__(16) float sh_q[D_];
    __shared__ __align__(16) float sh_k[D_];
    __shared__ float sc[S_];
    __shared__ float sb[S_];
    __shared__ __align__(16) float pvp[16][D_];
    __shared__ float redm[8], reds[8];

    const int bh = b * H_ + h;
    const size_t rowbase = ((size_t)bh * S_ + s) * (size_t)(S_ * D_);
    const float* gq = spq + rowbase;
    const float* gk = spk + rowbase;

    {
        const unsigned int sq0 = smem_u32(&stq[0][0]);
        const unsigned int sk0 = smem_u32(&stk[0][0]);
        cpasync16(sq0 + tid * 16,           gq + tid * 4);
        cpasync16(sq0 + (tid + 256) * 16,   gq + (tid + 256) * 4);
        cpasync16(sk0 + tid * 16,           gk + tid * 4);
        cpasync16(sk0 + (tid + 256) * 16,   gk + (tid + 256) * 4);
    }
    asm volatile("cp.async.commit_group;" ::: "memory");

    {
        const float* qrow = qh + (size_t)(b * S_ + s) * HID_ + h * D_;
        const float* krow = kh + (size_t)(b * S_ + s) * HID_ + h * D_;
        if (tid < D_)            sh_q[tid]      = qrow[tid];
        else if (tid < 2 * D_)   sh_k[tid - D_] = krow[tid - D_];
        sb[tid] = abias[((size_t)bh * S_ + s) * S_ + tid];
    }
    __syncthreads();

    const float4 q4 = reinterpret_cast<const float4*>(sh_q)[l16];
    const float4 k4 = reinterpret_cast<const float4*>(sh_k)[l16];
    const unsigned long long q01 = pack2(q4.x, q4.y);
    const unsigned long long q23 = pack2(q4.z, q4.w);
    const unsigned long long k01 = pack2(k4.x, k4.y);
    const unsigned long long k23 = pack2(k4.z, k4.w);

    for (int j = 0; j < S_ / TT_; j++) {
        const int buf = j & 1;
        if (j + 1 < S_ / TT_) {
            const int nb = (j + 1) & 1;
            const float* gq1 = gq + (j + 1) * TT_ * D_;
            const float* gk1 = gk + (j + 1) * TT_ * D_;
            const unsigned int sq1 = smem_u32(&stq[nb][0]);
            const unsigned int sk1 = smem_u32(&stk[nb][0]);
            cpasync16(sq1 + tid * 16,         gq1 + tid * 4);
            cpasync16(sq1 + (tid + 256) * 16, gq1 + (tid + 256) * 4);
            cpasync16(sk1 + tid * 16,         gk1 + tid * 4);
            cpasync16(sk1 + (tid + 256) * 16, gk1 + (tid + 256) * 4);
        }
        asm volatile("cp.async.commit_group;" ::: "memory");
        asm volatile("cp.async.wait_group 1;" ::: "memory");
        __syncthreads();

        const ulonglong2* bq2 = reinterpret_cast<const ulonglong2*>(&stq[buf][0]);
        const ulonglong2* bk2 = reinterpret_cast<const ulonglong2*>(&stk[buf][0]);
        const int tlA = w * 4 + half;
        const int tlB = tlA + 2;
        const int tgA = j * TT_ + tlA;
        const int tgB = j * TT_ + tlB;

        const ulonglong2 kkA = reinterpret_cast<const ulonglong2*>(
            kh + (size_t)(b * S_ + tgA) * HID_ + h * D_)[l16];
        const ulonglong2 kkB = reinterpret_cast<const ulonglong2*>(
            kh + (size_t)(b * S_ + tgB) * HID_ + h * D_)[l16];
        const ulonglong2 aqA = bq2[tlA * 16 + l16];
        const ulonglong2 akA = bk2[tlA * 16 + l16];
        const ulonglong2 aqB = bq2[tlB * 16 + l16];
        const ulonglong2 akB = bk2[tlB * 16 + l16];

        unsigned long long pA = mul2(q01, add2(kkA.x, aqA.x));
        ffma2(pA, q23, add2(kkA.y, aqA.y));
        ffma2(pA, k01, akA.x);
        ffma2(pA, k23, akA.y);
        unsigned long long pB = mul2(q01, add2(kkB.x, aqB.x));
        ffma2(pB, q23, add2(kkB.y, aqB.y));
        ffma2(pB, k01, akB.x);
        ffma2(pB, k23, akB.y);

        const float2 fA = unpack2(pA);
        const float2 fB = unpack2(pB);
        float a = fA.x + fA.y;
        float c = fB.x + fB.y;
        #pragma unroll
        for (int o = 8; o > 0; o >>= 1) {
            a += __shfl_xor_sync(0xffffffffu, a, o);
            c += __shfl_xor_sync(0xffffffffu, c, o);
        }
        if (l16 == 0) {
            sc[tgA] = a * SCALE_ + sb[tgA];
            sc[tgB] = c * SCALE_ + sb[tgB];
        }
        __syncthreads();
    }

    const float v0 = sc[tid];
    float m = v0;
    #pragma unroll
    for (int o = 16; o > 0; o >>= 1) m = fmaxf(m, __shfl_xor_sync(0xffffffffu, m, o));
    if (lane == 0) redm[w] = m;
    __syncthreads();
    float gm = redm[0];
    #pragma unroll
    for (int j = 1; j < 8; j++) gm = fmaxf(gm, redm[j]);

    const float e = __expf(v0 - gm);
    sc[tid] = e;
    float sum = e;
    #pragma unroll
    for (int o = 16; o > 0; o >>= 1) sum += __shfl_xor_sync(0xffffffffu, sum, o);
    if (lane == 0) reds[w] = sum;
    __syncthreads();
    float tot = reds[0];
    #pragma unroll
    for (int j = 1; j < 8; j++) tot += reds[j];
    const float inv = 1.0f / tot;

    const int g  = tid >> 4;
    const int ld = tid & 15;
    const float* vbase = vh + (size_t)(b * S_) * HID_ + h * D_;
    unsigned long long acc01 = 0ull, acc23 = 0ull;
    #pragma unroll
    for (int i = 0; i < 16; i++) {
        const int t = g * 16 + i;
        const float wt = sc[t];
        const unsigned long long w2 = pack2(wt, wt);
        const ulonglong2 v2 = reinterpret_cast<const ulonglong2*>(
            vbase + (size_t)t * HID_)[ld];
        ffma2(acc01, w2, v2.x);
        ffma2(acc23, w2, v2.y);
    }
    {
        const float2 a01 = unpack2(acc01);
        const float2 a23 = unpack2(acc23);
        float4 o; o.x = a01.x; o.y = a01.y; o.z = a23.x; o.w = a23.y;
        *reinterpret_cast<float4*>(&pvp[g][ld * 4]) = o;
    }
    __syncthreads();

    const int d  = tid & 63;
    const int gq4 = tid >> 6;
    const float part = pvp[gq4 * 4 + 0][d] + pvp[gq4 * 4 + 1][d]
                     + pvp[gq4 * 4 + 2][d] + pvp[gq4 * 4 + 3][d];
    __syncthreads();
    pvp[gq4][d] = part;
    __syncthreads();

    if (tid < D_) {
        const float r = (pvp[0][tid] + pvp[1][tid] + pvp[2][tid] + pvp[3][tid]) * inv;
        xo[(size_t)(b * S_ + s) * HID_ + h * D_ + tid] = r;
    }
}

// ---------------------------------------------------------------------------
// Launch  (4 launches/call: qkv, attn, o-part, o-reduce)
// ---------------------------------------------------------------------------
extern "C" void kernel_launch(void* const* d_in, const int* in_sizes, int n_in,
                              void* d_out, int out_size)
{
    const float* q    = (const float*)d_in[0];
    const float* k    = (const float*)d_in[1];
    const float* v    = (const float*)d_in[2];
    const float* ab   = (const float*)d_in[3];
    const float* spq  = (const float*)d_in[4];
    const float* spk  = (const float*)d_in[5];
    const float* Wq   = (const float*)d_in[6];
    const float* bq   = (const float*)d_in[7];
    const float* Wk   = (const float*)d_in[8];
    const float* bk   = (const float*)d_in[9];
    const float* Wv   = (const float*)d_in[10];
    const float* bv   = (const float*)d_in[11];
    const float* Wo   = (const float*)d_in[12];
    const float* bo   = (const float*)d_in[13];
    float* out        = (float*)d_out;

    void *pq = nullptr, *pk = nullptr, *pv = nullptr, *px = nullptr, *pp = nullptr;
    cudaGetSymbolAddress(&pq, g_q);
    cudaGetSymbolAddress(&pk, g_k);
    cudaGetSymbolAddress(&pv, g_v);
    cudaGetSymbolAddress(&px, g_x);
    cudaGetSymbolAddress(&pp, g_part);

    // ---- QKV projections: full-K, bias fused, one launch (384 CTAs) ----
    G3 qkv;
    qkv.A[0] = q;  qkv.A[1] = k;  qkv.A[2] = v;
    qkv.W[0] = Wq; qkv.W[1] = Wk; qkv.W[2] = Wv;
    qkv.bias[0] = bq; qkv.bias[1] = bk; qkv.bias[2] = bv;
    qkv.C[0] = (float*)pq; qkv.C[1] = (float*)pk; qkv.C[2] = (float*)pv;
    gemm64_db_kernel<<<dim3(HID_ / 64, M_ / 64, 3), 256>>>(
        qkv, (float*)pp, 1, 512, HID_, HID_);

    // ---- attention: cp.async-pipelined, one CTA per (b,h,s) ----
    const dim3 ga(S_, H_, B_);    // 8192 CTAs
    attn_pipe_kernel<<<ga, 256>>>((const float*)pq, (const float*)pk, (const float*)pv,
                                  ab, spq, spk, (float*)px);

    // ---- O projection: split-K2 (256 CTAs) + reduce ----
    G3 og;
    og.A[0] = (const float*)px; og.A[1] = og.A[0]; og.A[2] = og.A[0];
    og.W[0] = Wo; og.W[1] = Wo; og.W[2] = Wo;
    og.bias[0] = bo; og.bias[1] = bo; og.bias[2] = bo;
    og.C[0] = out; og.C[1] = out; og.C[2] = out;
    gemm64_db_kernel<<<dim3(HID_ / 64, M_ / 64, 2), 256>>>(
        og, (float*)pp, 2, 256, HID_, HID_);

    RedPtrs r2;
    r2.bias[0] = bo; r2.bias[1] = bo; r2.bias[2] = bo;
    r2.out[0] = out; r2.out[1] = out; r2.out[2] = out;
    reduce_bias_kernel<<<dim3(M_ * HID_ / 4 / 256, 1), 256>>>((const float*)pp, r2, 2);
}